// round 6
// baseline (speedup 1.0000x reference)
#include <cuda_runtime.h>

// ============================================================================
// Longformer attention, full fp32.
//   Q = x@Wq+bq ; K = x@Wk+bk ; V = x@Wv+bv      (split-head layout [B,H,S,d])
//   banded attention (window 256, global token 0), online softmax
//   out = att@Wo + bo
// ============================================================================

constexpr int D_MODEL = 1024;
constexpr int S_LEN   = 2048;
constexpr int BATCH   = 2;
constexpr int NHEADS  = 16;
constexpr int DHEAD   = 64;
constexpr int M_TOK   = BATCH * S_LEN;   // 4096
constexpr int WIN     = 256;

// scratch (device globals: no allocation allowed)
__device__ float g_Q[BATCH * NHEADS * S_LEN * DHEAD];
__device__ float g_K[BATCH * NHEADS * S_LEN * DHEAD];
__device__ float g_V[BATCH * NHEADS * S_LEN * DHEAD];
__device__ float g_att[M_TOK * D_MODEL];

// ----------------------------------------------------------------------------
// SGEMM: C = A[M=4096,K=1024] * W[K=1024,N=1024] + bias
// 128x128 block tile, BK=16, 256 threads, 8x8 per-thread tile, double buffered.
// SPLIT=true  : write [B,H,S,d] split-head layout
// SPLIT=false : write plain row-major [M,N]
// ----------------------------------------------------------------------------
template<bool SPLIT>
__global__ __launch_bounds__(256, 2)
void sgemm_bias(const float* __restrict__ A, const float* __restrict__ W,
                const float* __restrict__ bias, float* __restrict__ C)
{
    constexpr int K   = D_MODEL;
    constexpr int N   = D_MODEL;
    constexpr int LDA = 132;           // 128 + 4 pad: conflict-light transpose stores

    __shared__ float As[2][16 * LDA];
    __shared__ float Ws[2][16 * 128];

    const int tid = threadIdx.x;
    const int bm  = blockIdx.y * 128;
    const int bn  = blockIdx.x * 128;
    const int tx  = tid & 15;          // N dir
    const int ty  = tid >> 4;          // M dir

    const int a_row = tid >> 2;        // 0..63
    const int a_col = (tid & 3) << 2;  // 0,4,8,12
    const int w_row = tid >> 5;        // 0..7
    const int w_col = (tid & 31) << 2; // 0..124

    const float* Ap = A + (size_t)(bm + a_row) * K + a_col;
    const float* Wp = W + (size_t)w_row * N + bn + w_col;

    float acc[8][8];
#pragma unroll
    for (int i = 0; i < 8; ++i)
#pragma unroll
        for (int j = 0; j < 8; ++j) acc[i][j] = 0.f;

    float4 a0 = *(const float4*)Ap;
    float4 a1 = *(const float4*)(Ap + 64 * K);
    float4 w0 = *(const float4*)Wp;
    float4 w1 = *(const float4*)(Wp + 8 * N);

    // store tile 0
    {
        float* as = As[0];
        as[(a_col + 0) * LDA + a_row]      = a0.x;
        as[(a_col + 1) * LDA + a_row]      = a0.y;
        as[(a_col + 2) * LDA + a_row]      = a0.z;
        as[(a_col + 3) * LDA + a_row]      = a0.w;
        as[(a_col + 0) * LDA + a_row + 64] = a1.x;
        as[(a_col + 1) * LDA + a_row + 64] = a1.y;
        as[(a_col + 2) * LDA + a_row + 64] = a1.z;
        as[(a_col + 3) * LDA + a_row + 64] = a1.w;
        *(float4*)&Ws[0][w_row * 128 + w_col]       = w0;
        *(float4*)&Ws[0][(w_row + 8) * 128 + w_col] = w1;
    }
    __syncthreads();

    int buf = 0;
    for (int t = 0; t < K / 16; ++t) {
        if (t + 1 < K / 16) {            // prefetch next tile to registers
            const float* Ap2 = Ap + (t + 1) * 16;
            a0 = *(const float4*)Ap2;
            a1 = *(const float4*)(Ap2 + 64 * K);
            const float* Wp2 = Wp + (size_t)(t + 1) * 16 * N;
            w0 = *(const float4*)Wp2;
            w1 = *(const float4*)(Wp2 + 8 * N);
        }
        const float* as = As[buf];
        const float* ws = Ws[buf];
#pragma unroll
        for (int kk = 0; kk < 16; ++kk) {
            float ar[8], wr[8];
            *(float4*)&ar[0] = *(const float4*)&as[kk * LDA + ty * 8];
            *(float4*)&ar[4] = *(const float4*)&as[kk * LDA + ty * 8 + 4];
            *(float4*)&wr[0] = *(const float4*)&ws[kk * 128 + tx * 8];
            *(float4*)&wr[4] = *(const float4*)&ws[kk * 128 + tx * 8 + 4];
#pragma unroll
            for (int i = 0; i < 8; ++i)
#pragma unroll
                for (int j = 0; j < 8; ++j)
                    acc[i][j] = fmaf(ar[i], wr[j], acc[i][j]);
        }
        if (t + 1 < K / 16) {
            buf ^= 1;
            float* as2 = As[buf];
            as2[(a_col + 0) * LDA + a_row]      = a0.x;
            as2[(a_col + 1) * LDA + a_row]      = a0.y;
            as2[(a_col + 2) * LDA + a_row]      = a0.z;
            as2[(a_col + 3) * LDA + a_row]      = a0.w;
            as2[(a_col + 0) * LDA + a_row + 64] = a1.x;
            as2[(a_col + 1) * LDA + a_row + 64] = a1.y;
            as2[(a_col + 2) * LDA + a_row + 64] = a1.z;
            as2[(a_col + 3) * LDA + a_row + 64] = a1.w;
            *(float4*)&Ws[buf][w_row * 128 + w_col]       = w0;
            *(float4*)&Ws[buf][(w_row + 8) * 128 + w_col] = w1;
        }
        __syncthreads();
    }

    // epilogue: +bias, write out
    float bv[8];
    *(float4*)&bv[0] = *(const float4*)&bias[bn + tx * 8];
    *(float4*)&bv[4] = *(const float4*)&bias[bn + tx * 8 + 4];
#pragma unroll
    for (int i = 0; i < 8; ++i) {
        const int r = bm + ty * 8 + i;
#pragma unroll
        for (int j4 = 0; j4 < 8; j4 += 4) {
            float4 v;
            v.x = acc[i][j4 + 0] + bv[j4 + 0];
            v.y = acc[i][j4 + 1] + bv[j4 + 1];
            v.z = acc[i][j4 + 2] + bv[j4 + 2];
            v.w = acc[i][j4 + 3] + bv[j4 + 3];
            const int c = bn + tx * 8 + j4;
            if (SPLIT) {
                const int b  = r >> 11;          // / S_LEN
                const int s  = r & (S_LEN - 1);
                const int h  = c >> 6;           // / DHEAD
                const int dd = c & 63;
                *(float4*)&C[(((size_t)(b * NHEADS + h)) * S_LEN + s) * DHEAD + dd] = v;
            } else {
                *(float4*)&C[(size_t)r * N + c] = v;
            }
        }
    }
}

// ----------------------------------------------------------------------------
// Banded attention with online softmax.
// grid: (S/64 query tiles, B*H). 256 threads = 16x16 over a 64x64 tile.
// Each thread: 4 query rows x 4 key cols (scores) / 4 out dims (PV).
// Key chunks: chunk 0 (global col) + window chunks; q-block 0 does all chunks
// (row 0 is a global token attending everything).
// ----------------------------------------------------------------------------
__global__ __launch_bounds__(256, 2)
void attn_kernel()
{
    __shared__ float Qs[64 * 64];   // [row][dim], Q pre-scaled by 1/8
    __shared__ float KV[64 * 64];   // K transposed [dim][key], then V [key][dim]
    __shared__ float Ps[64 * 64];   // probabilities [row][key]

    const int tid = threadIdx.x;
    const int tx  = tid & 15;       // key cols / out dims
    const int ty  = tid >> 4;       // query rows
    const int bh  = blockIdx.y;     // b*16 + h
    const int qb  = blockIdx.x;
    const int qi0 = qb << 6;

    const float* Qh = g_Q + (size_t)bh * S_LEN * DHEAD;
    const float* Kh = g_K + (size_t)bh * S_LEN * DHEAD;
    const float* Vh = g_V + (size_t)bh * S_LEN * DHEAD;

    // load Q tile, pre-scaled by 1/sqrt(64)
#pragma unroll
    for (int it = 0; it < 4; ++it) {
        const int idx = tid + it * 256;
        const int r = idx >> 4, c4 = (idx & 15) << 2;
        float4 v = *(const float4*)(Qh + (size_t)(qi0 + r) * DHEAD + c4);
        v.x *= 0.125f; v.y *= 0.125f; v.z *= 0.125f; v.w *= 0.125f;
        *(float4*)&Qs[r * 64 + c4] = v;
    }

    float m_r[4], l_r[4], oacc[4][4];
#pragma unroll
    for (int i = 0; i < 4; ++i) {
        m_r[i] = -1e30f; l_r[i] = 0.f;
#pragma unroll
        for (int j = 0; j < 4; ++j) oacc[i][j] = 0.f;
    }

    int lo = qi0 - WIN;        if (lo < 0) lo = 0;
    int hi = qi0 + 63 + WIN;   if (hi > S_LEN - 1) hi = S_LEN - 1;
    int c_lo = lo >> 6;
    int c_hi = hi >> 6;
    if (qb == 0) c_hi = (S_LEN >> 6) - 1;   // row 0 is global: all chunks
    const int start = (c_lo < 1) ? 1 : c_lo;
    const int nch   = (c_hi - start + 1) + 1;   // +1 for chunk 0

    for (int ci = 0; ci < nch; ++ci) {
        const int ck = (ci == 0) ? 0 : (start + ci - 1);
        const int kb = ck << 6;

        __syncthreads();   // previous PV reads of KV done

        // load K chunk TRANSPOSED into KV: KV[dim][key]  (conflict-free stores)
#pragma unroll
        for (int it = 0; it < 4; ++it) {
            const int idx = tid + it * 256;
            const int kr = idx & 63;            // key
            const int c4 = (idx >> 6) << 2;     // dim group
            float4 v = *(const float4*)(Kh + (size_t)(kb + kr) * DHEAD + c4);
            KV[(c4 + 0) * 64 + kr] = v.x;
            KV[(c4 + 1) * 64 + kr] = v.y;
            KV[(c4 + 2) * 64 + kr] = v.z;
            KV[(c4 + 3) * 64 + kr] = v.w;
        }
        __syncthreads();

        // scores: s[i][j] = sum_kk Qs[row_i][kk] * Kt[kk][col_j]
        float s[4][4];
#pragma unroll
        for (int i = 0; i < 4; ++i)
#pragma unroll
            for (int j = 0; j < 4; ++j) s[i][j] = 0.f;

        const float* qrow = &Qs[(ty * 4) * 64];
#pragma unroll 8
        for (int kk = 0; kk < 64; ++kk) {
            const float4 k4 = *(const float4*)&KV[kk * 64 + tx * 4];
            const float kv[4] = { k4.x, k4.y, k4.z, k4.w };
            const float qv[4] = { qrow[kk], qrow[64 + kk], qrow[128 + kk], qrow[192 + kk] };
#pragma unroll
            for (int i = 0; i < 4; ++i)
#pragma unroll
                for (int j = 0; j < 4; ++j)
                    s[i][j] = fmaf(qv[i], kv[j], s[i][j]);
        }

        // mask + online softmax (row groups = 16-lane warp halves)
#pragma unroll
        for (int i = 0; i < 4; ++i) {
            const int r = qi0 + ty * 4 + i;
            float mx = -1e30f;
#pragma unroll
            for (int j = 0; j < 4; ++j) {
                const int c = kb + tx * 4 + j;
                int d = r - c; d = (d < 0) ? -d : d;
                const bool ok = (d <= WIN) | (r == 0) | (c == 0);
                if (!ok) s[i][j] = -1e30f;
                mx = fmaxf(mx, s[i][j]);
            }
#pragma unroll
            for (int off = 8; off >= 1; off >>= 1)
                mx = fmaxf(mx, __shfl_xor_sync(0xffffffffu, mx, off));
            const float mnew = fmaxf(m_r[i], mx);
            const float cf   = __expf(m_r[i] - mnew);
            m_r[i] = mnew;
            float p[4];
            float rs = 0.f;
#pragma unroll
            for (int j = 0; j < 4; ++j) {
                p[j] = (s[i][j] > -1e29f) ? __expf(s[i][j] - mnew) : 0.f;
                rs += p[j];
            }
            *(float4*)&Ps[(ty * 4 + i) * 64 + tx * 4] = make_float4(p[0], p[1], p[2], p[3]);
#pragma unroll
            for (int off = 8; off >= 1; off >>= 1)
                rs += __shfl_xor_sync(0xffffffffu, rs, off);
            l_r[i] = l_r[i] * cf + rs;
#pragma unroll
            for (int jd = 0; jd < 4; ++jd) oacc[i][jd] *= cf;
        }
        __syncthreads();   // Ps visible; KV (K) reads done

        // load V chunk (natural [key][dim])
#pragma unroll
        for (int it = 0; it < 4; ++it) {
            const int idx = tid + it * 256;
            const int r = idx >> 4, c4 = (idx & 15) << 2;
            *(float4*)&KV[r * 64 + c4] =
                *(const float4*)(Vh + (size_t)(kb + r) * DHEAD + c4);
        }
        __syncthreads();

        // PV: oacc[i][d] += Ps[row_i][j] * V[j][dim_d]
        const float* prow = &Ps[(ty * 4) * 64];
#pragma unroll 8
        for (int j = 0; j < 64; ++j) {
            const float4 v4 = *(const float4*)&KV[j * 64 + tx * 4];
            const float vv[4] = { v4.x, v4.y, v4.z, v4.w };
            const float pv[4] = { prow[j], prow[64 + j], prow[128 + j], prow[192 + j] };
#pragma unroll
            for (int i = 0; i < 4; ++i)
#pragma unroll
                for (int d = 0; d < 4; ++d)
                    oacc[i][d] = fmaf(pv[i], vv[d], oacc[i][d]);
        }
    }

    // write normalized output to token-major [B,S, H*d]
    const int b = bh >> 4, h = bh & 15;
#pragma unroll
    for (int i = 0; i < 4; ++i) {
        const int r = qi0 + ty * 4 + i;
        const float inv = 1.f / l_r[i];
        const float4 o = make_float4(oacc[i][0] * inv, oacc[i][1] * inv,
                                     oacc[i][2] * inv, oacc[i][3] * inv);
        *(float4*)&g_att[((size_t)(b * S_LEN + r)) * D_MODEL + h * DHEAD + tx * 4] = o;
    }
}

// ----------------------------------------------------------------------------
extern "C" void kernel_launch(void* const* d_in, const int* in_sizes, int n_in,
                              void* d_out, int out_size)
{
    (void)in_sizes; (void)n_in; (void)out_size;
    const float* x  = (const float*)d_in[0];
    const float* Wq = (const float*)d_in[1];
    const float* bq = (const float*)d_in[2];
    const float* Wk = (const float*)d_in[3];
    const float* bk = (const float*)d_in[4];
    const float* Wv = (const float*)d_in[5];
    const float* bv = (const float*)d_in[6];
    const float* Wo = (const float*)d_in[7];
    const float* bo = (const float*)d_in[8];
    float* out = (float*)d_out;

    float *Qp, *Kp, *Vp, *Ap;
    cudaGetSymbolAddress((void**)&Qp, g_Q);
    cudaGetSymbolAddress((void**)&Kp, g_K);
    cudaGetSymbolAddress((void**)&Vp, g_V);
    cudaGetSymbolAddress((void**)&Ap, g_att);

    const dim3 gg(D_MODEL / 128, M_TOK / 128);   // (8, 32)
    sgemm_bias<true><<<gg, 256>>>(x, Wq, bq, Qp);
    sgemm_bias<true><<<gg, 256>>>(x, Wk, bk, Kp);
    sgemm_bias<true><<<gg, 256>>>(x, Wv, bv, Vp);
    attn_kernel<<<dim3(S_LEN / 64, BATCH * NHEADS), 256>>>();
    sgemm_bias<false><<<gg, 256>>>(Ap, Wo, bo, out);
}

// round 7
// speedup vs baseline: 1.5757x; 1.5757x over previous
#include <cuda_runtime.h>
#include <cuda_bf16.h>
#include <cstdint>

// ============================================================================
// Longformer attention.
//   GEMMs on bf16 tensor cores with hi/lo split (3 products ~= fp32 accuracy)
//   banded attention (window 256, global token 0) in fp32, online softmax
// ============================================================================

constexpr int D_MODEL = 1024;
constexpr int S_LEN   = 2048;
constexpr int BATCH   = 2;
constexpr int NHEADS  = 16;
constexpr int DHEAD   = 64;
constexpr int M_TOK   = BATCH * S_LEN;   // 4096
constexpr int WIN     = 256;

// scratch (device globals: no allocation allowed)
__device__ float g_Q[BATCH * NHEADS * S_LEN * DHEAD];
__device__ float g_K[BATCH * NHEADS * S_LEN * DHEAD];
__device__ float g_V[BATCH * NHEADS * S_LEN * DHEAD];
__device__ __nv_bfloat16 g_xh[M_TOK * D_MODEL];
__device__ __nv_bfloat16 g_xl[M_TOK * D_MODEL];
__device__ __nv_bfloat16 g_wh[4 * D_MODEL * D_MODEL];
__device__ __nv_bfloat16 g_wl[4 * D_MODEL * D_MODEL];
__device__ __nv_bfloat16 g_ah[M_TOK * D_MODEL];   // attention out, hi
__device__ __nv_bfloat16 g_al[M_TOK * D_MODEL];   // attention out, lo

// ----------------------------------------------------------------------------
// fp32 -> bf16 hi + bf16 lo (residual). hi+lo carries ~16 mantissa bits.
// ----------------------------------------------------------------------------
__global__ void split_kernel(const float* __restrict__ s,
                             __nv_bfloat16* __restrict__ h,
                             __nv_bfloat16* __restrict__ l, int n)
{
    const int i = (blockIdx.x * blockDim.x + threadIdx.x) * 4;
    if (i >= n) return;
    float4 v = *(const float4*)(s + i);
    float a[4] = { v.x, v.y, v.z, v.w };
    __align__(8) __nv_bfloat16 hh[4], ll[4];
#pragma unroll
    for (int j = 0; j < 4; ++j) {
        hh[j] = __float2bfloat16(a[j]);
        ll[j] = __float2bfloat16(a[j] - __bfloat162float(hh[j]));
    }
    *(uint2*)&h[i] = *(uint2*)hh;
    *(uint2*)&l[i] = *(uint2*)ll;
}

// ----------------------------------------------------------------------------
// mma helpers
// ----------------------------------------------------------------------------
__device__ __forceinline__ uint32_t smem_u32(const void* p) {
    return (uint32_t)__cvta_generic_to_shared(p);
}
__device__ __forceinline__ void ldsm_x4(uint32_t (&r)[4], uint32_t addr) {
    asm volatile("ldmatrix.sync.aligned.m8n8.x4.shared.b16 {%0,%1,%2,%3}, [%4];"
                 : "=r"(r[0]), "=r"(r[1]), "=r"(r[2]), "=r"(r[3]) : "r"(addr));
}
__device__ __forceinline__ void ldsm_x4_t(uint32_t (&r)[4], uint32_t addr) {
    asm volatile("ldmatrix.sync.aligned.m8n8.x4.trans.shared.b16 {%0,%1,%2,%3}, [%4];"
                 : "=r"(r[0]), "=r"(r[1]), "=r"(r[2]), "=r"(r[3]) : "r"(addr));
}
__device__ __forceinline__ void mma16816(float (&d)[4], const uint32_t (&a)[4],
                                         uint32_t b0, uint32_t b1) {
    asm volatile("mma.sync.aligned.m16n8k16.row.col.f32.bf16.bf16.f32 "
                 "{%0,%1,%2,%3}, {%4,%5,%6,%7}, {%8,%9}, {%0,%1,%2,%3};"
                 : "+f"(d[0]), "+f"(d[1]), "+f"(d[2]), "+f"(d[3])
                 : "r"(a[0]), "r"(a[1]), "r"(a[2]), "r"(a[3]), "r"(b0), "r"(b1));
}

// ----------------------------------------------------------------------------
// bf16x3-split GEMM: C[M=4096, N=1024] = (Ah+Al)(Bh+Bl) + bias  (drop Al*Bl)
// 128x128 block tile, KSTEP=16, 256 threads = 8 warps (4m x 2n), warp 32x64.
// SPLIT=true writes [B,H,S,d]; else row-major [M,N].
// ----------------------------------------------------------------------------
template<bool SPLIT>
__global__ __launch_bounds__(256, 2)
void gemm_bf16x3(const __nv_bfloat16* __restrict__ Ah, const __nv_bfloat16* __restrict__ Al,
                 const __nv_bfloat16* __restrict__ Bh, const __nv_bfloat16* __restrict__ Bl,
                 const float* __restrict__ bias, float* __restrict__ C)
{
    constexpr int K   = D_MODEL;
    constexpr int N   = D_MODEL;
    constexpr int LDA = 24;    // 16 + 8 pad : conflict-free LDSM (48B row stride)
    constexpr int LDB = 136;   // 128 + 8 pad: conflict-free LDSM (272B row stride)

    __shared__ __nv_bfloat16 As[2][2][128 * LDA];   // [buf][hi/lo]
    __shared__ __nv_bfloat16 Bs[2][2][16 * LDB];

    const int tid  = threadIdx.x;
    const int lane = tid & 31;
    const int w    = tid >> 5;
    const int wm   = w >> 1;            // 0..3
    const int wn   = w & 1;             // 0..1
    const int bm   = blockIdx.y * 128;
    const int bn   = blockIdx.x * 128;

    // global load mapping
    const int arow = tid >> 1, acol = (tid & 1) * 8;
    const int brow = tid >> 4, bcol = (tid & 15) * 8;
    const __nv_bfloat16* Aph = Ah + (size_t)(bm + arow) * K + acol;
    const __nv_bfloat16* Apl = Al + (size_t)(bm + arow) * K + acol;
    const __nv_bfloat16* Bph = Bh + (size_t)brow * N + bn + bcol;
    const __nv_bfloat16* Bpl = Bl + (size_t)brow * N + bn + bcol;
    const int a_soff = arow * LDA + acol;
    const int b_soff = brow * LDB + bcol;

    // fragment smem addresses
    const int lr = lane & 15, lc = lane >> 4;
    uint32_t aAddr[2][2][2];   // [buf][part][mt]
    uint32_t bAddr[2][2][4];   // [buf][part][nt]
#pragma unroll
    for (int b2 = 0; b2 < 2; ++b2)
#pragma unroll
        for (int p = 0; p < 2; ++p) {
            uint32_t ab = smem_u32(&As[b2][p][0]);
            uint32_t bb = smem_u32(&Bs[b2][p][0]);
#pragma unroll
            for (int mt = 0; mt < 2; ++mt)
                aAddr[b2][p][mt] = ab + ((wm * 32 + mt * 16 + lr) * LDA + lc * 8) * 2;
#pragma unroll
            for (int nt = 0; nt < 4; ++nt)
                bAddr[b2][p][nt] = bb + (lr * LDB + wn * 64 + nt * 16 + lc * 8) * 2;
        }

    float c[2][8][4];
#pragma unroll
    for (int mt = 0; mt < 2; ++mt)
#pragma unroll
        for (int cn = 0; cn < 8; ++cn)
#pragma unroll
            for (int e = 0; e < 4; ++e) c[mt][cn][e] = 0.f;

    // stage 0
    *(uint4*)&As[0][0][a_soff] = *(const uint4*)Aph;
    *(uint4*)&As[0][1][a_soff] = *(const uint4*)Apl;
    *(uint4*)&Bs[0][0][b_soff] = *(const uint4*)Bph;
    *(uint4*)&Bs[0][1][b_soff] = *(const uint4*)Bpl;
    __syncthreads();

    int buf = 0;
    for (int t = 0; t < K / 16; ++t) {
        uint4 rah, ral, rbh, rbl;
        const bool pf = (t + 1) < K / 16;
        if (pf) {
            rah = *(const uint4*)(Aph + (t + 1) * 16);
            ral = *(const uint4*)(Apl + (t + 1) * 16);
            rbh = *(const uint4*)(Bph + (size_t)(t + 1) * 16 * N);
            rbl = *(const uint4*)(Bpl + (size_t)(t + 1) * 16 * N);
        }

        uint32_t a_h[2][4], a_l[2][4];
#pragma unroll
        for (int mt = 0; mt < 2; ++mt) {
            ldsm_x4(a_h[mt], aAddr[buf][0][mt]);
            ldsm_x4(a_l[mt], aAddr[buf][1][mt]);
        }
#pragma unroll
        for (int nt = 0; nt < 4; ++nt) {
            uint32_t b_h[4], b_l[4];
            ldsm_x4_t(b_h, bAddr[buf][0][nt]);
            ldsm_x4_t(b_l, bAddr[buf][1][nt]);
#pragma unroll
            for (int hh = 0; hh < 2; ++hh) {
                const int cn = nt * 2 + hh;
#pragma unroll
                for (int mt = 0; mt < 2; ++mt) {
                    mma16816(c[mt][cn], a_h[mt], b_h[2 * hh], b_h[2 * hh + 1]);
                    mma16816(c[mt][cn], a_h[mt], b_l[2 * hh], b_l[2 * hh + 1]);
                    mma16816(c[mt][cn], a_l[mt], b_h[2 * hh], b_h[2 * hh + 1]);
                }
            }
        }

        if (pf) {
            const int nb = buf ^ 1;
            *(uint4*)&As[nb][0][a_soff] = rah;
            *(uint4*)&As[nb][1][a_soff] = ral;
            *(uint4*)&Bs[nb][0][b_soff] = rbh;
            *(uint4*)&Bs[nb][1][b_soff] = rbl;
        }
        __syncthreads();
        buf ^= 1;
    }

    // epilogue
    const int r_base = bm + wm * 32;
    const int c_base = bn + wn * 64;
#pragma unroll
    for (int mt = 0; mt < 2; ++mt) {
#pragma unroll
        for (int cn = 0; cn < 8; ++cn) {
            const int r0 = r_base + mt * 16 + (lane >> 2);
            const int c0 = c_base + cn * 8 + (lane & 3) * 2;
            const float b0 = bias[c0], b1 = bias[c0 + 1];
            float2 v0 = make_float2(c[mt][cn][0] + b0, c[mt][cn][1] + b1);
            float2 v1 = make_float2(c[mt][cn][2] + b0, c[mt][cn][3] + b1);
            if (SPLIT) {
                const int bb = r0 >> 11, h = c0 >> 6, dd = c0 & 63;
                const int s0 = r0 & (S_LEN - 1);
                float* base = &C[(((size_t)(bb * NHEADS + h)) * S_LEN) * DHEAD + dd];
                *(float2*)(base + (size_t)s0 * DHEAD)       = v0;
                *(float2*)(base + (size_t)(s0 + 8) * DHEAD) = v1;
            } else {
                *(float2*)&C[(size_t)r0 * N + c0]       = v0;
                *(float2*)&C[(size_t)(r0 + 8) * N + c0] = v1;
            }
        }
    }
}

// ----------------------------------------------------------------------------
// Banded attention, fp32, online softmax. 64x64 tiles, 256 threads (16x16).
// Q stored TRANSPOSED in smem -> QK loop reads 1 broadcast float4 + 1 K float4.
// PV reads P as row-major float4 (broadcast). Output written as bf16 hi/lo.
// ----------------------------------------------------------------------------
__global__ __launch_bounds__(256, 2)
void attn_kernel()
{
    __shared__ float Qt[64 * 64];   // [dim][row], pre-scaled by 1/8
    __shared__ float KV[64 * 64];   // K transposed [dim][key], then V [key][dim]
    __shared__ float Ps[64 * 64];   // probabilities [row][key]

    const int tid = threadIdx.x;
    const int tx  = tid & 15;       // key cols / out dims
    const int ty  = tid >> 4;       // query rows
    const int bh  = blockIdx.y;
    const int qb  = blockIdx.x;
    const int qi0 = qb << 6;

    const float* Qh = g_Q + (size_t)bh * S_LEN * DHEAD;
    const float* Kh = g_K + (size_t)bh * S_LEN * DHEAD;
    const float* Vh = g_V + (size_t)bh * S_LEN * DHEAD;

    // load Q transposed (lanes run along row r -> conflict-free stores)
#pragma unroll
    for (int it = 0; it < 4; ++it) {
        const int idx = tid + it * 256;
        const int r = idx & 63;
        const int c4 = (idx >> 6) << 2;
        float4 v = *(const float4*)(Qh + (size_t)(qi0 + r) * DHEAD + c4);
        Qt[(c4 + 0) * 64 + r] = v.x * 0.125f;
        Qt[(c4 + 1) * 64 + r] = v.y * 0.125f;
        Qt[(c4 + 2) * 64 + r] = v.z * 0.125f;
        Qt[(c4 + 3) * 64 + r] = v.w * 0.125f;
    }

    float m_r[4], l_r[4], oacc[4][4];
#pragma unroll
    for (int i = 0; i < 4; ++i) {
        m_r[i] = -1e30f; l_r[i] = 0.f;
#pragma unroll
        for (int j = 0; j < 4; ++j) oacc[i][j] = 0.f;
    }

    int lo = qi0 - WIN;        if (lo < 0) lo = 0;
    int hi = qi0 + 63 + WIN;   if (hi > S_LEN - 1) hi = S_LEN - 1;
    int c_lo = lo >> 6;
    int c_hi = hi >> 6;
    if (qb == 0) c_hi = (S_LEN >> 6) - 1;   // row 0 is global: all chunks
    const int start = (c_lo < 1) ? 1 : c_lo;
    const int nch   = (c_hi - start + 1) + 1;   // +1 for chunk 0

    for (int ci = 0; ci < nch; ++ci) {
        const int ck = (ci == 0) ? 0 : (start + ci - 1);
        const int kb = ck << 6;

        __syncthreads();   // previous PV reads of KV done (also covers Qt init)

        // K chunk TRANSPOSED: KV[dim][key], conflict-free stores
#pragma unroll
        for (int it = 0; it < 4; ++it) {
            const int idx = tid + it * 256;
            const int kr = idx & 63;
            const int c4 = (idx >> 6) << 2;
            float4 v = *(const float4*)(Kh + (size_t)(kb + kr) * DHEAD + c4);
            KV[(c4 + 0) * 64 + kr] = v.x;
            KV[(c4 + 1) * 64 + kr] = v.y;
            KV[(c4 + 2) * 64 + kr] = v.z;
            KV[(c4 + 3) * 64 + kr] = v.w;
        }
        __syncthreads();

        // scores: both operands float4 along the reduced dim
        float s[4][4];
#pragma unroll
        for (int i = 0; i < 4; ++i)
#pragma unroll
            for (int j = 0; j < 4; ++j) s[i][j] = 0.f;

#pragma unroll 4
        for (int kk = 0; kk < 64; ++kk) {
            float qv[4], kv[4];
            *(float4*)qv = *(const float4*)&Qt[kk * 64 + ty * 4];   // 1 wf (broadcast)
            *(float4*)kv = *(const float4*)&KV[kk * 64 + tx * 4];   // 2 wf
#pragma unroll
            for (int i = 0; i < 4; ++i)
#pragma unroll
                for (int j = 0; j < 4; ++j)
                    s[i][j] = fmaf(qv[i], kv[j], s[i][j]);
        }

        // mask + online softmax (16-lane row groups = warp halves)
#pragma unroll
        for (int i = 0; i < 4; ++i) {
            const int r = qi0 + ty * 4 + i;
            float mx = -1e30f;
#pragma unroll
            for (int j = 0; j < 4; ++j) {
                const int cc = kb + tx * 4 + j;
                int d = r - cc; d = (d < 0) ? -d : d;
                const bool ok = (d <= WIN) | (r == 0) | (cc == 0);
                if (!ok) s[i][j] = -1e30f;
                mx = fmaxf(mx, s[i][j]);
            }
#pragma unroll
            for (int off = 8; off >= 1; off >>= 1)
                mx = fmaxf(mx, __shfl_xor_sync(0xffffffffu, mx, off));
            const float mnew = fmaxf(m_r[i], mx);
            const float cf   = __expf(m_r[i] - mnew);
            m_r[i] = mnew;
            float p[4], rs = 0.f;
#pragma unroll
            for (int j = 0; j < 4; ++j) {
                p[j] = (s[i][j] > -1e29f) ? __expf(s[i][j] - mnew) : 0.f;
                rs += p[j];
            }
            *(float4*)&Ps[(ty * 4 + i) * 64 + tx * 4] = make_float4(p[0], p[1], p[2], p[3]);
#pragma unroll
            for (int off = 8; off >= 1; off >>= 1)
                rs += __shfl_xor_sync(0xffffffffu, rs, off);
            l_r[i] = l_r[i] * cf + rs;
#pragma unroll
            for (int jd = 0; jd < 4; ++jd) oacc[i][jd] *= cf;
        }
        __syncthreads();   // Ps visible; KV(K) reads done

        // V chunk [key][dim]
#pragma unroll
        for (int it = 0; it < 4; ++it) {
            const int idx = tid + it * 256;
            const int r = idx >> 4, c4 = (idx & 15) << 2;
            *(float4*)&KV[r * 64 + c4] =
                *(const float4*)(Vh + (size_t)(kb + r) * DHEAD + c4);
        }
        __syncthreads();

        // PV: P read as float4 along j (broadcast)
#pragma unroll 2
        for (int jj = 0; jj < 64; jj += 4) {
            float pr[4][4];
#pragma unroll
            for (int i = 0; i < 4; ++i)
                *(float4*)&pr[i][0] = *(const float4*)&Ps[(ty * 4 + i) * 64 + jj];  // 1 wf
#pragma unroll
            for (int dj = 0; dj < 4; ++dj) {
                float vv[4];
                *(float4*)vv = *(const float4*)&KV[(jj + dj) * 64 + tx * 4];        // 2 wf
#pragma unroll
                for (int i = 0; i < 4; ++i)
#pragma unroll
                    for (int d = 0; d < 4; ++d)
                        oacc[i][d] = fmaf(pr[i][dj], vv[d], oacc[i][d]);
            }
        }
    }

    // write normalized output as bf16 hi/lo split, token-major [B,S,H*d]
    const int b = bh >> 4, h = bh & 15;
#pragma unroll
    for (int i = 0; i < 4; ++i) {
        const int r = qi0 + ty * 4 + i;
        const float inv = 1.f / l_r[i];
        __align__(8) __nv_bfloat16 hh[4], ll[4];
#pragma unroll
        for (int d = 0; d < 4; ++d) {
            const float o = oacc[i][d] * inv;
            hh[d] = __float2bfloat16(o);
            ll[d] = __float2bfloat16(o - __bfloat162float(hh[d]));
        }
        const size_t base = ((size_t)(b * S_LEN + r)) * D_MODEL + h * DHEAD + tx * 4;
        *(uint2*)&g_ah[base] = *(uint2*)hh;
        *(uint2*)&g_al[base] = *(uint2*)ll;
    }
}

// ----------------------------------------------------------------------------
extern "C" void kernel_launch(void* const* d_in, const int* in_sizes, int n_in,
                              void* d_out, int out_size)
{
    (void)in_sizes; (void)n_in; (void)out_size;
    const float* x  = (const float*)d_in[0];
    const float* Wq = (const float*)d_in[1];
    const float* bq = (const float*)d_in[2];
    const float* Wk = (const float*)d_in[3];
    const float* bk = (const float*)d_in[4];
    const float* Wv = (const float*)d_in[5];
    const float* bv = (const float*)d_in[6];
    const float* Wo = (const float*)d_in[7];
    const float* bo = (const float*)d_in[8];
    float* out = (float*)d_out;

    float *Qp, *Kp, *Vp;
    __nv_bfloat16 *xh, *xl, *wh, *wl, *ah, *al;
    cudaGetSymbolAddress((void**)&Qp, g_Q);
    cudaGetSymbolAddress((void**)&Kp, g_K);
    cudaGetSymbolAddress((void**)&Vp, g_V);
    cudaGetSymbolAddress((void**)&xh, g_xh);
    cudaGetSymbolAddress((void**)&xl, g_xl);
    cudaGetSymbolAddress((void**)&wh, g_wh);
    cudaGetSymbolAddress((void**)&wl, g_wl);
    cudaGetSymbolAddress((void**)&ah, g_ah);
    cudaGetSymbolAddress((void**)&al, g_al);

    constexpr int NW = D_MODEL * D_MODEL;   // 1M elems per weight

    split_kernel<<<M_TOK * D_MODEL / 1024, 256>>>(x, xh, xl, M_TOK * D_MODEL);
    split_kernel<<<NW / 1024, 256>>>(Wq, wh + 0 * NW, wl + 0 * NW, NW);
    split_kernel<<<NW / 1024, 256>>>(Wk, wh + 1 * NW, wl + 1 * NW, NW);
    split_kernel<<<NW / 1024, 256>>>(Wv, wh + 2 * NW, wl + 2 * NW, NW);
    split_kernel<<<NW / 1024, 256>>>(Wo, wh + 3 * NW, wl + 3 * NW, NW);

    const dim3 gg(D_MODEL / 128, M_TOK / 128);   // (8, 32)
    gemm_bf16x3<true><<<gg, 256>>>(xh, xl, wh + 0 * NW, wl + 0 * NW, bq, Qp);
    gemm_bf16x3<true><<<gg, 256>>>(xh, xl, wh + 1 * NW, wl + 1 * NW, bk, Kp);
    gemm_bf16x3<true><<<gg, 256>>>(xh, xl, wh + 2 * NW, wl + 2 * NW, bv, Vp);

    attn_kernel<<<dim3(S_LEN / 64, BATCH * NHEADS), 256>>>();

    gemm_bf16x3<false><<<gg, 256>>>(ah, al, wh + 3 * NW, wl + 3 * NW, bo, out);
}

// round 11
// speedup vs baseline: 2.4422x; 1.5500x over previous
#include <cuda_runtime.h>
#include <cuda_bf16.h>
#include <cstdint>

// ============================================================================
// Longformer attention. All heavy math on mma.sync bf16 with hi/lo split
// (3 products ~= fp32 accuracy). Flash-style attention, P kept in registers.
// Weights are used in ORIGINAL [K,N] layout (validated R6/R7 GEMM config).
// ============================================================================

constexpr int D_MODEL = 1024;
constexpr int S_LEN   = 2048;
constexpr int BATCH   = 2;
constexpr int NHEADS  = 16;
constexpr int DHEAD   = 64;
constexpr int M_TOK   = BATCH * S_LEN;   // 4096
constexpr int WIN     = 256;

// scratch (device globals: no allocation allowed)
__device__ __nv_bfloat16 g_xh[M_TOK * D_MODEL];
__device__ __nv_bfloat16 g_xl[M_TOK * D_MODEL];
__device__ __nv_bfloat16 g_wh[4 * D_MODEL * D_MODEL];   // W hi [K,N]
__device__ __nv_bfloat16 g_wl[4 * D_MODEL * D_MODEL];   // W lo [K,N]
__device__ __nv_bfloat16 g_qh[BATCH * NHEADS * S_LEN * DHEAD];  // [bh][s][d]
__device__ __nv_bfloat16 g_ql[BATCH * NHEADS * S_LEN * DHEAD];
__device__ __nv_bfloat16 g_kh[BATCH * NHEADS * DHEAD * S_LEN];  // [bh][d][s]  (transposed)
__device__ __nv_bfloat16 g_kl[BATCH * NHEADS * DHEAD * S_LEN];
__device__ __nv_bfloat16 g_vh[BATCH * NHEADS * S_LEN * DHEAD];  // [bh][s][d]
__device__ __nv_bfloat16 g_vl[BATCH * NHEADS * S_LEN * DHEAD];
__device__ __nv_bfloat16 g_ah[M_TOK * D_MODEL];   // attention out hi [tok][model]
__device__ __nv_bfloat16 g_al[M_TOK * D_MODEL];   // attention out lo

// ----------------------------------------------------------------------------
// helpers
// ----------------------------------------------------------------------------
__device__ __forceinline__ uint32_t smem_u32(const void* p) {
    return (uint32_t)__cvta_generic_to_shared(p);
}
__device__ __forceinline__ void ldsm_x4(uint32_t (&r)[4], uint32_t addr) {
    asm volatile("ldmatrix.sync.aligned.m8n8.x4.shared.b16 {%0,%1,%2,%3}, [%4];"
                 : "=r"(r[0]), "=r"(r[1]), "=r"(r[2]), "=r"(r[3]) : "r"(addr));
}
__device__ __forceinline__ void ldsm_x4_t(uint32_t (&r)[4], uint32_t addr) {
    asm volatile("ldmatrix.sync.aligned.m8n8.x4.trans.shared.b16 {%0,%1,%2,%3}, [%4];"
                 : "=r"(r[0]), "=r"(r[1]), "=r"(r[2]), "=r"(r[3]) : "r"(addr));
}
__device__ __forceinline__ void mma16816(float (&d)[4], const uint32_t (&a)[4],
                                         uint32_t b0, uint32_t b1) {
    asm volatile("mma.sync.aligned.m16n8k16.row.col.f32.bf16.bf16.f32 "
                 "{%0,%1,%2,%3}, {%4,%5,%6,%7}, {%8,%9}, {%0,%1,%2,%3};"
                 : "+f"(d[0]), "+f"(d[1]), "+f"(d[2]), "+f"(d[3])
                 : "r"(a[0]), "r"(a[1]), "r"(a[2]), "r"(a[3]), "r"(b0), "r"(b1));
}
__device__ __forceinline__ uint32_t pack2(__nv_bfloat16 a, __nv_bfloat16 b) {
    uint16_t x = *(uint16_t*)&a, y = *(uint16_t*)&b;
    return (uint32_t)x | ((uint32_t)y << 16);
}
__device__ __forceinline__ void split1(float v, __nv_bfloat16& h, __nv_bfloat16& l) {
    h = __float2bfloat16(v);
    l = __float2bfloat16(v - __bfloat162float(h));
}

// ----------------------------------------------------------------------------
// fp32 -> bf16 hi + lo residual
// ----------------------------------------------------------------------------
__global__ void split_kernel(const float* __restrict__ s,
                             __nv_bfloat16* __restrict__ h,
                             __nv_bfloat16* __restrict__ l, int n)
{
    const int i = (blockIdx.x * blockDim.x + threadIdx.x) * 4;
    if (i >= n) return;
    float4 v = *(const float4*)(s + i);
    float a[4] = { v.x, v.y, v.z, v.w };
    __align__(8) __nv_bfloat16 hh[4], ll[4];
#pragma unroll
    for (int j = 0; j < 4; ++j) split1(a[j], hh[j], ll[j]);
    *(uint2*)&h[i] = *(uint2*)hh;
    *(uint2*)&l[i] = *(uint2*)ll;
}

// ----------------------------------------------------------------------------
// bf16x3-split GEMM (validated R7 core): C = (Ah+Al)(Bh+Bl) + bias, B=[K,N]
// MODE 0: fp32 row-major [M,N]          (final projection -> d_out)
// MODE 1: bf16 hi/lo split-head [bh][s][d]   (Q, V)
// MODE 2: bf16 hi/lo transposed  [bh][d][s]  (K)
// ----------------------------------------------------------------------------
template<int MODE>
__global__ __launch_bounds__(256, 2)
void gemm_bf16x3(const __nv_bfloat16* __restrict__ Ah, const __nv_bfloat16* __restrict__ Al,
                 const __nv_bfloat16* __restrict__ Bh, const __nv_bfloat16* __restrict__ Bl,
                 const float* __restrict__ bias,
                 float* __restrict__ Cf,
                 __nv_bfloat16* __restrict__ Ch, __nv_bfloat16* __restrict__ Cl)
{
    constexpr int K   = D_MODEL;
    constexpr int N   = D_MODEL;
    constexpr int LDA = 24;    // 16 + 8 pad
    constexpr int LDB = 136;   // 128 + 8 pad

    __shared__ __nv_bfloat16 As[2][2][128 * LDA];   // [buf][hi/lo]
    __shared__ __nv_bfloat16 Bs[2][2][16 * LDB];

    const int tid  = threadIdx.x;
    const int lane = tid & 31;
    const int w    = tid >> 5;
    const int wm   = w >> 1;
    const int wn   = w & 1;
    const int bm   = blockIdx.y * 128;
    const int bn   = blockIdx.x * 128;

    const int arow = tid >> 1, acol = (tid & 1) * 8;
    const int brow = tid >> 4, bcol = (tid & 15) * 8;
    const __nv_bfloat16* Aph = Ah + (size_t)(bm + arow) * K + acol;
    const __nv_bfloat16* Apl = Al + (size_t)(bm + arow) * K + acol;
    const __nv_bfloat16* Bph = Bh + (size_t)brow * N + bn + bcol;   // B = W [K,N]
    const __nv_bfloat16* Bpl = Bl + (size_t)brow * N + bn + bcol;
    const int a_soff = arow * LDA + acol;
    const int b_soff = brow * LDB + bcol;

    const int lr = lane & 15, lc = lane >> 4;
    uint32_t aAddr[2][2][2];
    uint32_t bAddr[2][2][4];
#pragma unroll
    for (int b2 = 0; b2 < 2; ++b2)
#pragma unroll
        for (int p = 0; p < 2; ++p) {
            uint32_t ab = smem_u32(&As[b2][p][0]);
            uint32_t bb = smem_u32(&Bs[b2][p][0]);
#pragma unroll
            for (int mt = 0; mt < 2; ++mt)
                aAddr[b2][p][mt] = ab + ((wm * 32 + mt * 16 + lr) * LDA + lc * 8) * 2;
#pragma unroll
            for (int nt = 0; nt < 4; ++nt)
                bAddr[b2][p][nt] = bb + (lr * LDB + wn * 64 + nt * 16 + lc * 8) * 2;
        }

    float c[2][8][4];
#pragma unroll
    for (int mt = 0; mt < 2; ++mt)
#pragma unroll
        for (int cn = 0; cn < 8; ++cn)
#pragma unroll
            for (int e = 0; e < 4; ++e) c[mt][cn][e] = 0.f;

    *(uint4*)&As[0][0][a_soff] = *(const uint4*)Aph;
    *(uint4*)&As[0][1][a_soff] = *(const uint4*)Apl;
    *(uint4*)&Bs[0][0][b_soff] = *(const uint4*)Bph;
    *(uint4*)&Bs[0][1][b_soff] = *(const uint4*)Bpl;
    __syncthreads();

    int buf = 0;
    for (int t = 0; t < K / 16; ++t) {
        uint4 rah, ral, rbh, rbl;
        const bool pf = (t + 1) < K / 16;
        if (pf) {
            rah = *(const uint4*)(Aph + (t + 1) * 16);
            ral = *(const uint4*)(Apl + (t + 1) * 16);
            rbh = *(const uint4*)(Bph + (size_t)(t + 1) * 16 * N);
            rbl = *(const uint4*)(Bpl + (size_t)(t + 1) * 16 * N);
        }

        uint32_t a_h[2][4], a_l[2][4];
#pragma unroll
        for (int mt = 0; mt < 2; ++mt) {
            ldsm_x4(a_h[mt], aAddr[buf][0][mt]);
            ldsm_x4(a_l[mt], aAddr[buf][1][mt]);
        }
#pragma unroll
        for (int nt = 0; nt < 4; ++nt) {
            uint32_t b_h[4], b_l[4];
            ldsm_x4_t(b_h, bAddr[buf][0][nt]);
            ldsm_x4_t(b_l, bAddr[buf][1][nt]);
#pragma unroll
            for (int hh = 0; hh < 2; ++hh) {
                const int cn = nt * 2 + hh;
#pragma unroll
                for (int mt = 0; mt < 2; ++mt) {
                    mma16816(c[mt][cn], a_h[mt], b_h[2 * hh], b_h[2 * hh + 1]);
                    mma16816(c[mt][cn], a_h[mt], b_l[2 * hh], b_l[2 * hh + 1]);
                    mma16816(c[mt][cn], a_l[mt], b_h[2 * hh], b_h[2 * hh + 1]);
                }
            }
        }

        if (pf) {
            const int nb = buf ^ 1;
            *(uint4*)&As[nb][0][a_soff] = rah;
            *(uint4*)&As[nb][1][a_soff] = ral;
            *(uint4*)&Bs[nb][0][b_soff] = rbh;
            *(uint4*)&Bs[nb][1][b_soff] = rbl;
        }
        __syncthreads();
        buf ^= 1;
    }

    // epilogue
    const int r_base = bm + wm * 32 + (lane >> 2);
    const int c_base = bn + wn * 64 + (lane & 3) * 2;
#pragma unroll
    for (int mt = 0; mt < 2; ++mt) {
#pragma unroll
        for (int cn = 0; cn < 8; ++cn) {
            const int r0 = r_base + mt * 16;
            const int c0 = c_base + cn * 8;
            const float b0 = bias[c0], b1 = bias[c0 + 1];
            const float v00 = c[mt][cn][0] + b0, v01 = c[mt][cn][1] + b1;  // row r0
            const float v10 = c[mt][cn][2] + b0, v11 = c[mt][cn][3] + b1;  // row r0+8
            if (MODE == 0) {
                *(float2*)&Cf[(size_t)r0 * N + c0]       = make_float2(v00, v01);
                *(float2*)&Cf[(size_t)(r0 + 8) * N + c0] = make_float2(v10, v11);
            } else if (MODE == 1) {
                const int h = c0 >> 6, dd = c0 & 63;
#pragma unroll
                for (int rr = 0; rr < 2; ++rr) {
                    const int r = r0 + rr * 8;
                    const int bb = r >> 11, s = r & (S_LEN - 1);
                    const size_t base = (((size_t)(bb * NHEADS + h)) * S_LEN + s) * DHEAD + dd;
                    const float x0 = rr ? v10 : v00, x1 = rr ? v11 : v01;
                    __nv_bfloat16 h0, l0, h1, l1;
                    split1(x0, h0, l0); split1(x1, h1, l1);
                    *(uint32_t*)&Ch[base] = pack2(h0, h1);
                    *(uint32_t*)&Cl[base] = pack2(l0, l1);
                }
            } else {  // MODE 2: [bh][d][s]
                const int h = c0 >> 6, dd = c0 & 63;
#pragma unroll
                for (int rr = 0; rr < 2; ++rr) {
                    const int r = r0 + rr * 8;
                    const int bb = r >> 11, s = r & (S_LEN - 1);
                    const size_t base = (((size_t)(bb * NHEADS + h)) * DHEAD + dd) * S_LEN + s;
                    const float x0 = rr ? v10 : v00, x1 = rr ? v11 : v01;
                    __nv_bfloat16 h0, l0, h1, l1;
                    split1(x0, h0, l0); split1(x1, h1, l1);
                    Ch[base] = h0; Ch[base + S_LEN] = h1;
                    Cl[base] = l0; Cl[base + S_LEN] = l1;
                }
            }
        }
    }
}

// ----------------------------------------------------------------------------
// Banded flash attention on mma.sync bf16 hi/lo. 4 warps, 64q x 64k tiles.
// Warp = 16 query rows. P stays in registers (QK d-frag == PV a-frag layout).
// ----------------------------------------------------------------------------
constexpr int ATT_LD   = 144;                 // bytes per smem row (64 bf16 + 8 pad)
constexpr int SM_QH = 0;
constexpr int SM_QL = SM_QH + 64 * ATT_LD;
constexpr int SM_KH = SM_QL + 64 * ATT_LD;
constexpr int SM_KL = SM_KH + 64 * ATT_LD;
constexpr int SM_VH = SM_KL + 64 * ATT_LD;
constexpr int SM_VL = SM_VH + 64 * ATT_LD;
constexpr int ATT_SMEM = SM_VL + 64 * ATT_LD; // 55296 B

__global__ __launch_bounds__(128)
void attn_kernel()
{
    extern __shared__ char sm[];
    const uint32_t sb = smem_u32(sm);
    const int tid  = threadIdx.x;
    const int lane = tid & 31;
    const int w    = tid >> 5;          // 0..3 : query rows w*16..w*16+15
    const int bh   = blockIdx.y;
    const int qb   = blockIdx.x;
    const int qi0  = qb << 6;

    const __nv_bfloat16* Qh = g_qh + (size_t)bh * S_LEN * DHEAD;
    const __nv_bfloat16* Ql = g_ql + (size_t)bh * S_LEN * DHEAD;
    const __nv_bfloat16* Kh = g_kh + (size_t)bh * DHEAD * S_LEN;
    const __nv_bfloat16* Kl = g_kl + (size_t)bh * DHEAD * S_LEN;
    const __nv_bfloat16* Vh = g_vh + (size_t)bh * S_LEN * DHEAD;
    const __nv_bfloat16* Vl = g_vl + (size_t)bh * S_LEN * DHEAD;

    // ---- load Q tile (rows qi0..qi0+63): 64 rows x 8 x 16B segments --------
#pragma unroll
    for (int it = 0; it < 4; ++it) {
        const int idx = tid + it * 128;          // 0..511
        const int row = idx >> 3, seg = idx & 7;
        *(uint4*)(sm + SM_QH + row * ATT_LD + seg * 16) =
            *(const uint4*)(Qh + (size_t)(qi0 + row) * DHEAD + seg * 8);
        *(uint4*)(sm + SM_QL + row * ATT_LD + seg * 16) =
            *(const uint4*)(Ql + (size_t)(qi0 + row) * DHEAD + seg * 8);
    }
    __syncthreads();

    // ---- Q fragments (constant across chunks) ------------------------------
    const int lr = lane & 15, lc = lane >> 4;
    uint32_t aqh[4][4], aql[4][4];
    {
        const uint32_t qoff = sb + (w * 16 + lr) * ATT_LD + lc * 16;
#pragma unroll
        for (int kt = 0; kt < 4; ++kt) {
            ldsm_x4(aqh[kt], qoff + SM_QH + kt * 32);
            ldsm_x4(aql[kt], qoff + SM_QL + kt * 32);
        }
    }

    const int row0 = qi0 + w * 16 + (lane >> 2);
    const int row1 = row0 + 8;
    const int colq = (lane & 3) * 2;

    float m0 = -1e30f, m1 = -1e30f, l0 = 0.f, l1 = 0.f;
    float o[8][4];
#pragma unroll
    for (int nt = 0; nt < 8; ++nt)
#pragma unroll
        for (int e = 0; e < 4; ++e) o[nt][e] = 0.f;

    // ---- chunk schedule ----------------------------------------------------
    int lo = qi0 - WIN;        if (lo < 0) lo = 0;
    int hi = qi0 + 63 + WIN;   if (hi > S_LEN - 1) hi = S_LEN - 1;
    int c_lo = lo >> 6;
    int c_hi = hi >> 6;
    if (qb == 0) c_hi = (S_LEN >> 6) - 1;   // row 0 is global: all chunks
    const int start = (c_lo < 1) ? 1 : c_lo;
    const int nch   = (c_hi - start + 1) + 1;

    const uint32_t kvoff = sb + lr * ATT_LD + lc * 16;

    for (int ci = 0; ci < nch; ++ci) {
        const int ck = (ci == 0) ? 0 : (start + ci - 1);
        const int kb = ck << 6;

        __syncthreads();   // previous chunk's ldsm reads complete
        // K chunk [d][key] (gmem already transposed) + V chunk [key][d]
#pragma unroll
        for (int it = 0; it < 4; ++it) {
            const int idx = tid + it * 128;      // 0..511
            const int row = idx >> 3, seg = idx & 7;
            *(uint4*)(sm + SM_KH + row * ATT_LD + seg * 16) =
                *(const uint4*)(Kh + (size_t)row * S_LEN + kb + seg * 8);
            *(uint4*)(sm + SM_KL + row * ATT_LD + seg * 16) =
                *(const uint4*)(Kl + (size_t)row * S_LEN + kb + seg * 8);
            *(uint4*)(sm + SM_VH + row * ATT_LD + seg * 16) =
                *(const uint4*)(Vh + (size_t)(kb + row) * DHEAD + seg * 8);
            *(uint4*)(sm + SM_VL + row * ATT_LD + seg * 16) =
                *(const uint4*)(Vl + (size_t)(kb + row) * DHEAD + seg * 8);
        }
        __syncthreads();

        // ---- scores: S = Q K^T -------------------------------------------
        float s[8][4];
#pragma unroll
        for (int nt = 0; nt < 8; ++nt)
#pragma unroll
            for (int e = 0; e < 4; ++e) s[nt][e] = 0.f;

#pragma unroll
        for (int nt4 = 0; nt4 < 4; ++nt4) {
#pragma unroll
            for (int kt = 0; kt < 4; ++kt) {
                uint32_t bk_h[4], bk_l[4];
                ldsm_x4_t(bk_h, kvoff + SM_KH + kt * (16 * ATT_LD) + nt4 * 32);
                ldsm_x4_t(bk_l, kvoff + SM_KL + kt * (16 * ATT_LD) + nt4 * 32);
#pragma unroll
                for (int hh = 0; hh < 2; ++hh) {
                    float (&sd)[4] = s[nt4 * 2 + hh];
                    mma16816(sd, aqh[kt], bk_h[2 * hh], bk_h[2 * hh + 1]);
                    mma16816(sd, aql[kt], bk_h[2 * hh], bk_h[2 * hh + 1]);
                    mma16816(sd, aqh[kt], bk_l[2 * hh], bk_l[2 * hh + 1]);
                }
            }
        }

        // ---- mask + scale + online softmax --------------------------------
        float mx0 = -1e30f, mx1 = -1e30f;
#pragma unroll
        for (int nt = 0; nt < 8; ++nt) {
            const int cb = kb + nt * 8 + colq;
#pragma unroll
            for (int oo = 0; oo < 2; ++oo) {
                const int cc = cb + oo;
                int d0 = row0 - cc; d0 = (d0 < 0) ? -d0 : d0;
                int d1 = row1 - cc; d1 = (d1 < 0) ? -d1 : d1;
                const bool ok0 = (d0 <= WIN) | (row0 == 0) | (cc == 0);
                const bool ok1 = (d1 <= WIN) | (row1 == 0) | (cc == 0);
                s[nt][oo]     = ok0 ? s[nt][oo]     * 0.125f : -1e30f;
                s[nt][2 + oo] = ok1 ? s[nt][2 + oo] * 0.125f : -1e30f;
                mx0 = fmaxf(mx0, s[nt][oo]);
                mx1 = fmaxf(mx1, s[nt][2 + oo]);
            }
        }
        mx0 = fmaxf(mx0, __shfl_xor_sync(0xffffffffu, mx0, 1));
        mx0 = fmaxf(mx0, __shfl_xor_sync(0xffffffffu, mx0, 2));
        mx1 = fmaxf(mx1, __shfl_xor_sync(0xffffffffu, mx1, 1));
        mx1 = fmaxf(mx1, __shfl_xor_sync(0xffffffffu, mx1, 2));

        const float mn0 = fmaxf(m0, mx0), mn1 = fmaxf(m1, mx1);
        const float cf0 = __expf(m0 - mn0), cf1 = __expf(m1 - mn1);
        m0 = mn0; m1 = mn1;

        float rs0 = 0.f, rs1 = 0.f;
#pragma unroll
        for (int nt = 0; nt < 8; ++nt) {
            s[nt][0] = __expf(s[nt][0] - mn0);
            s[nt][1] = __expf(s[nt][1] - mn0);
            s[nt][2] = __expf(s[nt][2] - mn1);
            s[nt][3] = __expf(s[nt][3] - mn1);
            rs0 += s[nt][0] + s[nt][1];
            rs1 += s[nt][2] + s[nt][3];
        }
        rs0 += __shfl_xor_sync(0xffffffffu, rs0, 1);
        rs0 += __shfl_xor_sync(0xffffffffu, rs0, 2);
        rs1 += __shfl_xor_sync(0xffffffffu, rs1, 1);
        rs1 += __shfl_xor_sync(0xffffffffu, rs1, 2);
        l0 = l0 * cf0 + rs0;
        l1 = l1 * cf1 + rs1;
#pragma unroll
        for (int nt = 0; nt < 8; ++nt) {
            o[nt][0] *= cf0; o[nt][1] *= cf0;
            o[nt][2] *= cf1; o[nt][3] *= cf1;
        }

        // ---- PV: O += P V  (P frags built in registers) -------------------
#pragma unroll
        for (int kt = 0; kt < 4; ++kt) {
            uint32_t ap_h[4], ap_l[4];
#pragma unroll
            for (int half = 0; half < 2; ++half) {
                const float* ps = s[2 * kt + half];
                __nv_bfloat16 h0, l0b, h1, l1b, h2, l2b, h3, l3b;
                split1(ps[0], h0, l0b); split1(ps[1], h1, l1b);
                split1(ps[2], h2, l2b); split1(ps[3], h3, l3b);
                ap_h[2 * half + 0] = pack2(h0, h1);
                ap_h[2 * half + 1] = pack2(h2, h3);
                ap_l[2 * half + 0] = pack2(l0b, l1b);
                ap_l[2 * half + 1] = pack2(l2b, l3b);
            }
            // a-frag order: {(r,k),(r+8,k),(r,k+8),(r+8,k+8)} — matches build above.
#pragma unroll
            for (int nd4 = 0; nd4 < 4; ++nd4) {
                uint32_t bv_h[4], bv_l[4];
                ldsm_x4_t(bv_h, kvoff + SM_VH + kt * (16 * ATT_LD) + nd4 * 32);
                ldsm_x4_t(bv_l, kvoff + SM_VL + kt * (16 * ATT_LD) + nd4 * 32);
#pragma unroll
                for (int hh = 0; hh < 2; ++hh) {
                    float (&od)[4] = o[nd4 * 2 + hh];
                    mma16816(od, ap_h, bv_h[2 * hh], bv_h[2 * hh + 1]);
                    mma16816(od, ap_l, bv_h[2 * hh], bv_h[2 * hh + 1]);
                    mma16816(od, ap_h, bv_l[2 * hh], bv_l[2 * hh + 1]);
                }
            }
        }
    }

    // ---- normalize + write bf16 hi/lo, token-major [B,S,H*d] ---------------
    const int b = bh >> 4, h = bh & 15;
    const float i0 = 1.f / l0, i1 = 1.f / l1;
#pragma unroll
    for (int nt = 0; nt < 8; ++nt) {
        const int dd = h * DHEAD + nt * 8 + colq;
        {
            const float x0 = o[nt][0] * i0, x1 = o[nt][1] * i0;
            __nv_bfloat16 h0, lo0, h1, lo1;
            split1(x0, h0, lo0); split1(x1, h1, lo1);
            const size_t base = ((size_t)(b * S_LEN + row0)) * D_MODEL + dd;
            *(uint32_t*)&g_ah[base] = pack2(h0, h1);
            *(uint32_t*)&g_al[base] = pack2(lo0, lo1);
        }
        {
            const float x0 = o[nt][2] * i1, x1 = o[nt][3] * i1;
            __nv_bfloat16 h0, lo0, h1, lo1;
            split1(x0, h0, lo0); split1(x1, h1, lo1);
            const size_t base = ((size_t)(b * S_LEN + row1)) * D_MODEL + dd;
            *(uint32_t*)&g_ah[base] = pack2(h0, h1);
            *(uint32_t*)&g_al[base] = pack2(lo0, lo1);
        }
    }
}

// ----------------------------------------------------------------------------
extern "C" void kernel_launch(void* const* d_in, const int* in_sizes, int n_in,
                              void* d_out, int out_size)
{
    (void)in_sizes; (void)n_in; (void)out_size;
    const float* x  = (const float*)d_in[0];
    const float* Wq = (const float*)d_in[1];
    const float* bq = (const float*)d_in[2];
    const float* Wk = (const float*)d_in[3];
    const float* bk = (const float*)d_in[4];
    const float* Wv = (const float*)d_in[5];
    const float* bv = (const float*)d_in[6];
    const float* Wo = (const float*)d_in[7];
    const float* bo = (const float*)d_in[8];
    float* out = (float*)d_out;

    __nv_bfloat16 *xh, *xl, *wh, *wl, *qh, *ql, *kh, *kl, *vh, *vl, *ah, *al;
    cudaGetSymbolAddress((void**)&xh, g_xh);
    cudaGetSymbolAddress((void**)&xl, g_xl);
    cudaGetSymbolAddress((void**)&wh, g_wh);
    cudaGetSymbolAddress((void**)&wl, g_wl);
    cudaGetSymbolAddress((void**)&qh, g_qh);
    cudaGetSymbolAddress((void**)&ql, g_ql);
    cudaGetSymbolAddress((void**)&kh, g_kh);
    cudaGetSymbolAddress((void**)&kl, g_kl);
    cudaGetSymbolAddress((void**)&vh, g_vh);
    cudaGetSymbolAddress((void**)&vl, g_vl);
    cudaGetSymbolAddress((void**)&ah, g_ah);
    cudaGetSymbolAddress((void**)&al, g_al);

    cudaFuncSetAttribute(attn_kernel, cudaFuncAttributeMaxDynamicSharedMemorySize, ATT_SMEM);

    constexpr int NW = D_MODEL * D_MODEL;

    split_kernel<<<M_TOK * D_MODEL / 1024, 256>>>(x, xh, xl, M_TOK * D_MODEL);
    split_kernel<<<NW / 1024, 256>>>(Wq, wh + 0 * NW, wl + 0 * NW, NW);
    split_kernel<<<NW / 1024, 256>>>(Wk, wh + 1 * NW, wl + 1 * NW, NW);
    split_kernel<<<NW / 1024, 256>>>(Wv, wh + 2 * NW, wl + 2 * NW, NW);
    split_kernel<<<NW / 1024, 256>>>(Wo, wh + 3 * NW, wl + 3 * NW, NW);

    const dim3 gg(D_MODEL / 128, M_TOK / 128);   // (8, 32)
    gemm_bf16x3<1><<<gg, 256>>>(xh, xl, wh + 0 * NW, wl + 0 * NW, bq, nullptr, qh, ql);
    gemm_bf16x3<2><<<gg, 256>>>(xh, xl, wh + 1 * NW, wl + 1 * NW, bk, nullptr, kh, kl);
    gemm_bf16x3<1><<<gg, 256>>>(xh, xl, wh + 2 * NW, wl + 2 * NW, bv, nullptr, vh, vl);

    attn_kernel<<<dim3(S_LEN / 64, BATCH * NHEADS), 128, ATT_SMEM>>>();

    gemm_bf16x3<0><<<gg, 256>>>(ah, al, wh + 3 * NW, wl + 3 * NW, bo, out, nullptr, nullptr);
}

// round 12
// speedup vs baseline: 3.0714x; 1.2576x over previous
#include <cuda_runtime.h>
#include <cuda_bf16.h>
#include <cuda_fp16.h>
#include <cstdint>

// ============================================================================
// Longformer attention.
//   Projections: fp16x2 GEMM  (A single fp16, W split fp16 hi/lo, 2 products)
//   Attention:   bf16x3 flash attention on mma.sync (unchanged from R11)
// ============================================================================

constexpr int D_MODEL = 1024;
constexpr int S_LEN   = 2048;
constexpr int BATCH   = 2;
constexpr int NHEADS  = 16;
constexpr int DHEAD   = 64;
constexpr int M_TOK   = BATCH * S_LEN;   // 4096
constexpr int WIN     = 256;

// scratch (device globals: no allocation allowed)
__device__ __half g_xh[M_TOK * D_MODEL];                 // x as fp16
__device__ __half g_wh[4 * D_MODEL * D_MODEL];           // W hi [K,N] fp16
__device__ __half g_wl[4 * D_MODEL * D_MODEL];           // W lo [K,N] fp16
__device__ __nv_bfloat16 g_qh[BATCH * NHEADS * S_LEN * DHEAD];  // [bh][s][d]
__device__ __nv_bfloat16 g_ql[BATCH * NHEADS * S_LEN * DHEAD];
__device__ __nv_bfloat16 g_kh[BATCH * NHEADS * DHEAD * S_LEN];  // [bh][d][s]
__device__ __nv_bfloat16 g_kl[BATCH * NHEADS * DHEAD * S_LEN];
__device__ __nv_bfloat16 g_vh[BATCH * NHEADS * S_LEN * DHEAD];  // [bh][s][d]
__device__ __nv_bfloat16 g_vl[BATCH * NHEADS * S_LEN * DHEAD];
__device__ __half g_att[M_TOK * D_MODEL];                // attention out fp16

// ----------------------------------------------------------------------------
// helpers
// ----------------------------------------------------------------------------
__device__ __forceinline__ uint32_t smem_u32(const void* p) {
    return (uint32_t)__cvta_generic_to_shared(p);
}
__device__ __forceinline__ void ldsm_x4(uint32_t (&r)[4], uint32_t addr) {
    asm volatile("ldmatrix.sync.aligned.m8n8.x4.shared.b16 {%0,%1,%2,%3}, [%4];"
                 : "=r"(r[0]), "=r"(r[1]), "=r"(r[2]), "=r"(r[3]) : "r"(addr));
}
__device__ __forceinline__ void ldsm_x4_t(uint32_t (&r)[4], uint32_t addr) {
    asm volatile("ldmatrix.sync.aligned.m8n8.x4.trans.shared.b16 {%0,%1,%2,%3}, [%4];"
                 : "=r"(r[0]), "=r"(r[1]), "=r"(r[2]), "=r"(r[3]) : "r"(addr));
}
// bf16 mma (attention)
__device__ __forceinline__ void mma16816(float (&d)[4], const uint32_t (&a)[4],
                                         uint32_t b0, uint32_t b1) {
    asm volatile("mma.sync.aligned.m16n8k16.row.col.f32.bf16.bf16.f32 "
                 "{%0,%1,%2,%3}, {%4,%5,%6,%7}, {%8,%9}, {%0,%1,%2,%3};"
                 : "+f"(d[0]), "+f"(d[1]), "+f"(d[2]), "+f"(d[3])
                 : "r"(a[0]), "r"(a[1]), "r"(a[2]), "r"(a[3]), "r"(b0), "r"(b1));
}
// fp16 mma (projections)
__device__ __forceinline__ void mma16816h(float (&d)[4], const uint32_t (&a)[4],
                                          uint32_t b0, uint32_t b1) {
    asm volatile("mma.sync.aligned.m16n8k16.row.col.f32.f16.f16.f32 "
                 "{%0,%1,%2,%3}, {%4,%5,%6,%7}, {%8,%9}, {%0,%1,%2,%3};"
                 : "+f"(d[0]), "+f"(d[1]), "+f"(d[2]), "+f"(d[3])
                 : "r"(a[0]), "r"(a[1]), "r"(a[2]), "r"(a[3]), "r"(b0), "r"(b1));
}
__device__ __forceinline__ uint32_t pack2(__nv_bfloat16 a, __nv_bfloat16 b) {
    uint16_t x = *(uint16_t*)&a, y = *(uint16_t*)&b;
    return (uint32_t)x | ((uint32_t)y << 16);
}
__device__ __forceinline__ uint32_t pack2h(__half a, __half b) {
    uint16_t x = *(uint16_t*)&a, y = *(uint16_t*)&b;
    return (uint32_t)x | ((uint32_t)y << 16);
}
__device__ __forceinline__ void split1(float v, __nv_bfloat16& h, __nv_bfloat16& l) {
    h = __float2bfloat16(v);
    l = __float2bfloat16(v - __bfloat162float(h));
}

// ----------------------------------------------------------------------------
// x: fp32 -> fp16 (single)
// ----------------------------------------------------------------------------
__global__ void splitx_kernel(const float* __restrict__ s, __half* __restrict__ h, int n)
{
    const int i = (blockIdx.x * blockDim.x + threadIdx.x) * 4;
    if (i >= n) return;
    float4 v = *(const float4*)(s + i);
    __align__(8) __half hh[4] = { __float2half(v.x), __float2half(v.y),
                                  __float2half(v.z), __float2half(v.w) };
    *(uint2*)&h[i] = *(uint2*)hh;
}

// ----------------------------------------------------------------------------
// W: fp32 -> fp16 hi + fp16 lo residual. All 4 weights in one launch (grid.y).
// ----------------------------------------------------------------------------
__global__ void splitw_kernel(const float* __restrict__ W0, const float* __restrict__ W1,
                              const float* __restrict__ W2, const float* __restrict__ W3,
                              __half* __restrict__ h, __half* __restrict__ l)
{
    constexpr int NW = D_MODEL * D_MODEL;
    const int wsel = blockIdx.y;
    const float* W = (wsel == 0) ? W0 : (wsel == 1) ? W1 : (wsel == 2) ? W2 : W3;
    const int i = (blockIdx.x * blockDim.x + threadIdx.x) * 4;
    if (i >= NW) return;
    float4 v = *(const float4*)(W + i);
    float a[4] = { v.x, v.y, v.z, v.w };
    __align__(8) __half hh[4], ll[4];
#pragma unroll
    for (int j = 0; j < 4; ++j) {
        hh[j] = __float2half(a[j]);
        ll[j] = __float2half(a[j] - __half2float(hh[j]));
    }
    const size_t o = (size_t)wsel * NW + i;
    *(uint2*)&h[o] = *(uint2*)hh;
    *(uint2*)&l[o] = *(uint2*)ll;
}

// ----------------------------------------------------------------------------
// fp16x2 GEMM: C[4096,1024] = A_fp16 * (Wh + Wl) + bias,  W = [K,N]
// 128x128 tile, KSTEP 16, 256 thr = 8 warps (4m x 2n), warp 32x64. 2 products.
// MODE 0: fp32 row-major [M,N]        (final projection -> d_out)
// MODE 1: bf16 hi/lo split-head [bh][s][d]   (Q, V)
// MODE 2: bf16 hi/lo transposed  [bh][d][s]  (K)
// ----------------------------------------------------------------------------
template<int MODE>
__global__ __launch_bounds__(256, 2)
void gemm_fp16x2(const __half* __restrict__ A,
                 const __half* __restrict__ Bh, const __half* __restrict__ Bl,
                 const float* __restrict__ bias,
                 float* __restrict__ Cf,
                 __nv_bfloat16* __restrict__ Ch, __nv_bfloat16* __restrict__ Cl)
{
    constexpr int K   = D_MODEL;
    constexpr int N   = D_MODEL;
    constexpr int LDA = 24;    // 16 + 8 pad
    constexpr int LDB = 136;   // 128 + 8 pad

    __shared__ __half As[2][128 * LDA];
    __shared__ __half Bs[2][2][16 * LDB];   // [buf][hi/lo]

    const int tid  = threadIdx.x;
    const int lane = tid & 31;
    const int w    = tid >> 5;
    const int wm   = w >> 1;
    const int wn   = w & 1;
    const int bm   = blockIdx.y * 128;
    const int bn   = blockIdx.x * 128;

    const int arow = tid >> 1, acol = (tid & 1) * 8;
    const int brow = tid >> 4, bcol = (tid & 15) * 8;
    const __half* Ap  = A  + (size_t)(bm + arow) * K + acol;
    const __half* Bph = Bh + (size_t)brow * N + bn + bcol;
    const __half* Bpl = Bl + (size_t)brow * N + bn + bcol;
    const int a_soff = arow * LDA + acol;
    const int b_soff = brow * LDB + bcol;

    const int lr = lane & 15, lc = lane >> 4;
    uint32_t aAddr[2][2];      // [buf][mt]
    uint32_t bAddr[2][2][4];   // [buf][part][nt]
#pragma unroll
    for (int b2 = 0; b2 < 2; ++b2) {
        uint32_t ab = smem_u32(&As[b2][0]);
#pragma unroll
        for (int mt = 0; mt < 2; ++mt)
            aAddr[b2][mt] = ab + ((wm * 32 + mt * 16 + lr) * LDA + lc * 8) * 2;
#pragma unroll
        for (int p = 0; p < 2; ++p) {
            uint32_t bb = smem_u32(&Bs[b2][p][0]);
#pragma unroll
            for (int nt = 0; nt < 4; ++nt)
                bAddr[b2][p][nt] = bb + (lr * LDB + wn * 64 + nt * 16 + lc * 8) * 2;
        }
    }

    float c[2][8][4];
#pragma unroll
    for (int mt = 0; mt < 2; ++mt)
#pragma unroll
        for (int cn = 0; cn < 8; ++cn)
#pragma unroll
            for (int e = 0; e < 4; ++e) c[mt][cn][e] = 0.f;

    *(uint4*)&As[0][a_soff]    = *(const uint4*)Ap;
    *(uint4*)&Bs[0][0][b_soff] = *(const uint4*)Bph;
    *(uint4*)&Bs[0][1][b_soff] = *(const uint4*)Bpl;
    __syncthreads();

    int buf = 0;
    for (int t = 0; t < K / 16; ++t) {
        uint4 ra, rbh, rbl;
        const bool pf = (t + 1) < K / 16;
        if (pf) {
            ra  = *(const uint4*)(Ap + (t + 1) * 16);
            rbh = *(const uint4*)(Bph + (size_t)(t + 1) * 16 * N);
            rbl = *(const uint4*)(Bpl + (size_t)(t + 1) * 16 * N);
        }

        uint32_t a_f[2][4];
#pragma unroll
        for (int mt = 0; mt < 2; ++mt) ldsm_x4(a_f[mt], aAddr[buf][mt]);
#pragma unroll
        for (int nt = 0; nt < 4; ++nt) {
            uint32_t b_h[4], b_l[4];
            ldsm_x4_t(b_h, bAddr[buf][0][nt]);
            ldsm_x4_t(b_l, bAddr[buf][1][nt]);
#pragma unroll
            for (int hh = 0; hh < 2; ++hh) {
                const int cn = nt * 2 + hh;
#pragma unroll
                for (int mt = 0; mt < 2; ++mt) {
                    mma16816h(c[mt][cn], a_f[mt], b_h[2 * hh], b_h[2 * hh + 1]);
                    mma16816h(c[mt][cn], a_f[mt], b_l[2 * hh], b_l[2 * hh + 1]);
                }
            }
        }

        if (pf) {
            const int nb = buf ^ 1;
            *(uint4*)&As[nb][a_soff]    = ra;
            *(uint4*)&Bs[nb][0][b_soff] = rbh;
            *(uint4*)&Bs[nb][1][b_soff] = rbl;
        }
        __syncthreads();
        buf ^= 1;
    }

    // epilogue
    const int r_base = bm + wm * 32 + (lane >> 2);
    const int c_base = bn + wn * 64 + (lane & 3) * 2;
#pragma unroll
    for (int mt = 0; mt < 2; ++mt) {
#pragma unroll
        for (int cn = 0; cn < 8; ++cn) {
            const int r0 = r_base + mt * 16;
            const int c0 = c_base + cn * 8;
            const float b0 = bias[c0], b1 = bias[c0 + 1];
            const float v00 = c[mt][cn][0] + b0, v01 = c[mt][cn][1] + b1;  // row r0
            const float v10 = c[mt][cn][2] + b0, v11 = c[mt][cn][3] + b1;  // row r0+8
            if (MODE == 0) {
                *(float2*)&Cf[(size_t)r0 * N + c0]       = make_float2(v00, v01);
                *(float2*)&Cf[(size_t)(r0 + 8) * N + c0] = make_float2(v10, v11);
            } else if (MODE == 1) {
                const int h = c0 >> 6, dd = c0 & 63;
#pragma unroll
                for (int rr = 0; rr < 2; ++rr) {
                    const int r = r0 + rr * 8;
                    const int bb = r >> 11, s = r & (S_LEN - 1);
                    const size_t base = (((size_t)(bb * NHEADS + h)) * S_LEN + s) * DHEAD + dd;
                    const float x0 = rr ? v10 : v00, x1 = rr ? v11 : v01;
                    __nv_bfloat16 h0, l0, h1, l1;
                    split1(x0, h0, l0); split1(x1, h1, l1);
                    *(uint32_t*)&Ch[base] = pack2(h0, h1);
                    *(uint32_t*)&Cl[base] = pack2(l0, l1);
                }
            } else {  // MODE 2: [bh][d][s]
                const int h = c0 >> 6, dd = c0 & 63;
#pragma unroll
                for (int rr = 0; rr < 2; ++rr) {
                    const int r = r0 + rr * 8;
                    const int bb = r >> 11, s = r & (S_LEN - 1);
                    const size_t base = (((size_t)(bb * NHEADS + h)) * DHEAD + dd) * S_LEN + s;
                    const float x0 = rr ? v10 : v00, x1 = rr ? v11 : v01;
                    __nv_bfloat16 h0, l0, h1, l1;
                    split1(x0, h0, l0); split1(x1, h1, l1);
                    Ch[base] = h0; Ch[base + S_LEN] = h1;
                    Cl[base] = l0; Cl[base + S_LEN] = l1;
                }
            }
        }
    }
}

// ----------------------------------------------------------------------------
// Banded flash attention on mma.sync bf16 hi/lo (R11-validated core).
// 4 warps, 64q x 64k tiles; P in registers. Output written as fp16 single.
// ----------------------------------------------------------------------------
constexpr int ATT_LD   = 144;                 // bytes per smem row (64 bf16 + 8 pad)
constexpr int SM_QH = 0;
constexpr int SM_QL = SM_QH + 64 * ATT_LD;
constexpr int SM_KH = SM_QL + 64 * ATT_LD;
constexpr int SM_KL = SM_KH + 64 * ATT_LD;
constexpr int SM_VH = SM_KL + 64 * ATT_LD;
constexpr int SM_VL = SM_VH + 64 * ATT_LD;
constexpr int ATT_SMEM = SM_VL + 64 * ATT_LD; // 55296 B

__global__ __launch_bounds__(128)
void attn_kernel()
{
    extern __shared__ char sm[];
    const uint32_t sb = smem_u32(sm);
    const int tid  = threadIdx.x;
    const int lane = tid & 31;
    const int w    = tid >> 5;          // 0..3 : query rows w*16..w*16+15
    const int bh   = blockIdx.y;
    const int qb   = blockIdx.x;
    const int qi0  = qb << 6;

    const __nv_bfloat16* Qh = g_qh + (size_t)bh * S_LEN * DHEAD;
    const __nv_bfloat16* Ql = g_ql + (size_t)bh * S_LEN * DHEAD;
    const __nv_bfloat16* Kh = g_kh + (size_t)bh * DHEAD * S_LEN;
    const __nv_bfloat16* Kl = g_kl + (size_t)bh * DHEAD * S_LEN;
    const __nv_bfloat16* Vh = g_vh + (size_t)bh * S_LEN * DHEAD;
    const __nv_bfloat16* Vl = g_vl + (size_t)bh * S_LEN * DHEAD;

    // ---- load Q tile (rows qi0..qi0+63): 64 rows x 8 x 16B segments --------
#pragma unroll
    for (int it = 0; it < 4; ++it) {
        const int idx = tid + it * 128;          // 0..511
        const int row = idx >> 3, seg = idx & 7;
        *(uint4*)(sm + SM_QH + row * ATT_LD + seg * 16) =
            *(const uint4*)(Qh + (size_t)(qi0 + row) * DHEAD + seg * 8);
        *(uint4*)(sm + SM_QL + row * ATT_LD + seg * 16) =
            *(const uint4*)(Ql + (size_t)(qi0 + row) * DHEAD + seg * 8);
    }
    __syncthreads();

    // ---- Q fragments (constant across chunks) ------------------------------
    const int lr = lane & 15, lc = lane >> 4;
    uint32_t aqh[4][4], aql[4][4];
    {
        const uint32_t qoff = sb + (w * 16 + lr) * ATT_LD + lc * 16;
#pragma unroll
        for (int kt = 0; kt < 4; ++kt) {
            ldsm_x4(aqh[kt], qoff + SM_QH + kt * 32);
            ldsm_x4(aql[kt], qoff + SM_QL + kt * 32);
        }
    }

    const int row0 = qi0 + w * 16 + (lane >> 2);
    const int row1 = row0 + 8;
    const int colq = (lane & 3) * 2;

    float m0 = -1e30f, m1 = -1e30f, l0 = 0.f, l1 = 0.f;
    float o[8][4];
#pragma unroll
    for (int nt = 0; nt < 8; ++nt)
#pragma unroll
        for (int e = 0; e < 4; ++e) o[nt][e] = 0.f;

    // ---- chunk schedule ----------------------------------------------------
    int lo = qi0 - WIN;        if (lo < 0) lo = 0;
    int hi = qi0 + 63 + WIN;   if (hi > S_LEN - 1) hi = S_LEN - 1;
    int c_lo = lo >> 6;
    int c_hi = hi >> 6;
    if (qb == 0) c_hi = (S_LEN >> 6) - 1;   // row 0 is global: all chunks
    const int start = (c_lo < 1) ? 1 : c_lo;
    const int nch   = (c_hi - start + 1) + 1;

    const uint32_t kvoff = sb + lr * ATT_LD + lc * 16;

    for (int ci = 0; ci < nch; ++ci) {
        const int ck = (ci == 0) ? 0 : (start + ci - 1);
        const int kb = ck << 6;

        __syncthreads();   // previous chunk's ldsm reads complete
        // K chunk [d][key] (gmem already transposed) + V chunk [key][d]
#pragma unroll
        for (int it = 0; it < 4; ++it) {
            const int idx = tid + it * 128;      // 0..511
            const int row = idx >> 3, seg = idx & 7;
            *(uint4*)(sm + SM_KH + row * ATT_LD + seg * 16) =
                *(const uint4*)(Kh + (size_t)row * S_LEN + kb + seg * 8);
            *(uint4*)(sm + SM_KL + row * ATT_LD + seg * 16) =
                *(const uint4*)(Kl + (size_t)row * S_LEN + kb + seg * 8);
            *(uint4*)(sm + SM_VH + row * ATT_LD + seg * 16) =
                *(const uint4*)(Vh + (size_t)(kb + row) * DHEAD + seg * 8);
            *(uint4*)(sm + SM_VL + row * ATT_LD + seg * 16) =
                *(const uint4*)(Vl + (size_t)(kb + row) * DHEAD + seg * 8);
        }
        __syncthreads();

        // ---- scores: S = Q K^T -------------------------------------------
        float s[8][4];
#pragma unroll
        for (int nt = 0; nt < 8; ++nt)
#pragma unroll
            for (int e = 0; e < 4; ++e) s[nt][e] = 0.f;

#pragma unroll
        for (int nt4 = 0; nt4 < 4; ++nt4) {
#pragma unroll
            for (int kt = 0; kt < 4; ++kt) {
                uint32_t bk_h[4], bk_l[4];
                ldsm_x4_t(bk_h, kvoff + SM_KH + kt * (16 * ATT_LD) + nt4 * 32);
                ldsm_x4_t(bk_l, kvoff + SM_KL + kt * (16 * ATT_LD) + nt4 * 32);
#pragma unroll
                for (int hh = 0; hh < 2; ++hh) {
                    float (&sd)[4] = s[nt4 * 2 + hh];
                    mma16816(sd, aqh[kt], bk_h[2 * hh], bk_h[2 * hh + 1]);
                    mma16816(sd, aql[kt], bk_h[2 * hh], bk_h[2 * hh + 1]);
                    mma16816(sd, aqh[kt], bk_l[2 * hh], bk_l[2 * hh + 1]);
                }
            }
        }

        // ---- mask + scale + online softmax --------------------------------
        float mx0 = -1e30f, mx1 = -1e30f;
#pragma unroll
        for (int nt = 0; nt < 8; ++nt) {
            const int cb = kb + nt * 8 + colq;
#pragma unroll
            for (int oo = 0; oo < 2; ++oo) {
                const int cc = cb + oo;
                int d0 = row0 - cc; d0 = (d0 < 0) ? -d0 : d0;
                int d1 = row1 - cc; d1 = (d1 < 0) ? -d1 : d1;
                const bool ok0 = (d0 <= WIN) | (row0 == 0) | (cc == 0);
                const bool ok1 = (d1 <= WIN) | (row1 == 0) | (cc == 0);
                s[nt][oo]     = ok0 ? s[nt][oo]     * 0.125f : -1e30f;
                s[nt][2 + oo] = ok1 ? s[nt][2 + oo] * 0.125f : -1e30f;
                mx0 = fmaxf(mx0, s[nt][oo]);
                mx1 = fmaxf(mx1, s[nt][2 + oo]);
            }
        }
        mx0 = fmaxf(mx0, __shfl_xor_sync(0xffffffffu, mx0, 1));
        mx0 = fmaxf(mx0, __shfl_xor_sync(0xffffffffu, mx0, 2));
        mx1 = fmaxf(mx1, __shfl_xor_sync(0xffffffffu, mx1, 1));
        mx1 = fmaxf(mx1, __shfl_xor_sync(0xffffffffu, mx1, 2));

        const float mn0 = fmaxf(m0, mx0), mn1 = fmaxf(m1, mx1);
        const float cf0 = __expf(m0 - mn0), cf1 = __expf(m1 - mn1);
        m0 = mn0; m1 = mn1;

        float rs0 = 0.f, rs1 = 0.f;
#pragma unroll
        for (int nt = 0; nt < 8; ++nt) {
            s[nt][0] = __expf(s[nt][0] - mn0);
            s[nt][1] = __expf(s[nt][1] - mn0);
            s[nt][2] = __expf(s[nt][2] - mn1);
            s[nt][3] = __expf(s[nt][3] - mn1);
            rs0 += s[nt][0] + s[nt][1];
            rs1 += s[nt][2] + s[nt][3];
        }
        rs0 += __shfl_xor_sync(0xffffffffu, rs0, 1);
        rs0 += __shfl_xor_sync(0xffffffffu, rs0, 2);
        rs1 += __shfl_xor_sync(0xffffffffu, rs1, 1);
        rs1 += __shfl_xor_sync(0xffffffffu, rs1, 2);
        l0 = l0 * cf0 + rs0;
        l1 = l1 * cf1 + rs1;
#pragma unroll
        for (int nt = 0; nt < 8; ++nt) {
            o[nt][0] *= cf0; o[nt][1] *= cf0;
            o[nt][2] *= cf1; o[nt][3] *= cf1;
        }

        // ---- PV: O += P V  (P frags built in registers) -------------------
#pragma unroll
        for (int kt = 0; kt < 4; ++kt) {
            uint32_t ap_h[4], ap_l[4];
#pragma unroll
            for (int half = 0; half < 2; ++half) {
                const float* ps = s[2 * kt + half];
                __nv_bfloat16 h0, l0b, h1, l1b, h2, l2b, h3, l3b;
                split1(ps[0], h0, l0b); split1(ps[1], h1, l1b);
                split1(ps[2], h2, l2b); split1(ps[3], h3, l3b);
                ap_h[2 * half + 0] = pack2(h0, h1);
                ap_h[2 * half + 1] = pack2(h2, h3);
                ap_l[2 * half + 0] = pack2(l0b, l1b);
                ap_l[2 * half + 1] = pack2(l2b, l3b);
            }
#pragma unroll
            for (int nd4 = 0; nd4 < 4; ++nd4) {
                uint32_t bv_h[4], bv_l[4];
                ldsm_x4_t(bv_h, kvoff + SM_VH + kt * (16 * ATT_LD) + nd4 * 32);
                ldsm_x4_t(bv_l, kvoff + SM_VL + kt * (16 * ATT_LD) + nd4 * 32);
#pragma unroll
                for (int hh = 0; hh < 2; ++hh) {
                    float (&od)[4] = o[nd4 * 2 + hh];
                    mma16816(od, ap_h, bv_h[2 * hh], bv_h[2 * hh + 1]);
                    mma16816(od, ap_l, bv_h[2 * hh], bv_h[2 * hh + 1]);
                    mma16816(od, ap_h, bv_l[2 * hh], bv_l[2 * hh + 1]);
                }
            }
        }
    }

    // ---- normalize + write fp16, token-major [B,S,H*d] ---------------------
    const int b = bh >> 4, h = bh & 15;
    const float i0 = 1.f / l0, i1 = 1.f / l1;
#pragma unroll
    for (int nt = 0; nt < 8; ++nt) {
        const int dd = h * DHEAD + nt * 8 + colq;
        {
            const size_t base = ((size_t)(b * S_LEN + row0)) * D_MODEL + dd;
            *(uint32_t*)&g_att[base] =
                pack2h(__float2half(o[nt][0] * i0), __float2half(o[nt][1] * i0));
        }
        {
            const size_t base = ((size_t)(b * S_LEN + row1)) * D_MODEL + dd;
            *(uint32_t*)&g_att[base] =
                pack2h(__float2half(o[nt][2] * i1), __float2half(o[nt][3] * i1));
        }
    }
}

// ----------------------------------------------------------------------------
extern "C" void kernel_launch(void* const* d_in, const int* in_sizes, int n_in,
                              void* d_out, int out_size)
{
    (void)in_sizes; (void)n_in; (void)out_size;
    const float* x  = (const float*)d_in[0];
    const float* Wq = (const float*)d_in[1];
    const float* bq = (const float*)d_in[2];
    const float* Wk = (const float*)d_in[3];
    const float* bk = (const float*)d_in[4];
    const float* Wv = (const float*)d_in[5];
    const float* bv = (const float*)d_in[6];
    const float* Wo = (const float*)d_in[7];
    const float* bo = (const float*)d_in[8];
    float* out = (float*)d_out;

    __half *xh, *wh, *wl, *att;
    __nv_bfloat16 *qh, *ql, *kh, *kl, *vh, *vl;
    cudaGetSymbolAddress((void**)&xh,  g_xh);
    cudaGetSymbolAddress((void**)&wh,  g_wh);
    cudaGetSymbolAddress((void**)&wl,  g_wl);
    cudaGetSymbolAddress((void**)&qh,  g_qh);
    cudaGetSymbolAddress((void**)&ql,  g_ql);
    cudaGetSymbolAddress((void**)&kh,  g_kh);
    cudaGetSymbolAddress((void**)&kl,  g_kl);
    cudaGetSymbolAddress((void**)&vh,  g_vh);
    cudaGetSymbolAddress((void**)&vl,  g_vl);
    cudaGetSymbolAddress((void**)&att, g_att);

    cudaFuncSetAttribute(attn_kernel, cudaFuncAttributeMaxDynamicSharedMemorySize, ATT_SMEM);

    constexpr int NW = D_MODEL * D_MODEL;

    splitx_kernel<<<M_TOK * D_MODEL / 1024, 256>>>(x, xh, M_TOK * D_MODEL);
    splitw_kernel<<<dim3(NW / 1024, 4), 256>>>(Wq, Wk, Wv, Wo, wh, wl);

    const dim3 gg(D_MODEL / 128, M_TOK / 128);   // (8, 32)
    gemm_fp16x2<1><<<gg, 256>>>(xh, wh + 0 * NW, wl + 0 * NW, bq, nullptr, qh, ql);
    gemm_fp16x2<2><<<gg, 256>>>(xh, wh + 1 * NW, wl + 1 * NW, bk, nullptr, kh, kl);
    gemm_fp16x2<1><<<gg, 256>>>(xh, wh + 2 * NW, wl + 2 * NW, bv, nullptr, vh, vl);

    attn_kernel<<<dim3(S_LEN / 64, BATCH * NHEADS), 128, ATT_SMEM>>>();

    gemm_fp16x2<0><<<gg, 256>>>(att, wh + 3 * NW, wl + 3 * NW, bo, out, nullptr, nullptr);
}